// round 2
// baseline (speedup 1.0000x reference)
#include <cuda_runtime.h>
#include <math.h>

// Problem dims
#define NXc 128
#define NYc 64
#define NMc 32
#define NDTc 32
#define NUc 32
#define NDc 32
#define NSTEPSc 1024
#define Bc 128
#define TPc 64

// Output offsets (in floats) for the flattened 11-tuple
#define OFF_X      ((size_t)0)
#define OFF_Y      ((size_t)16777216)
#define OFF_U      ((size_t)25165824)
#define OFF_SXMIN  ((size_t)29360128)
#define OFF_SXMAX  ((size_t)46137344)
#define OFF_SUMIN  ((size_t)62914560)
#define OFF_SUMAX  ((size_t)67108864)
#define OFF_SDXX   ((size_t)71303168)
#define OFF_SDXU   ((size_t)88080384)
#define OFF_SDXD   ((size_t)104857600)
#define OFF_SPECT  ((size_t)121634816)

// ---------------- scratch (module-scope device memory; no runtime allocs) ----
__device__ float g_WA[NXc * NXc];        // spectral A            (128x128)
__device__ float g_WC[NXc * NYc];        // spectral C            (128x64)
__device__ float g_WE[NDc * NXc];        // PF disturbance map    (32x128)
__device__ float g_WB[NUc * NXc];        // relu(w_B)             (32x128)
__device__ float g_bvec[NXc];            // x0_correct @ W_A
__device__ float g_x0[Bc * NXc];         // RNN final state per batch
__device__ float g_C[(size_t)NSTEPSc * Bc * NXc]; // Bu+Ed+bvec (64 MB)
__device__ float g_acc[8];               // Gram/Frobenius accumulators

__device__ __forceinline__ float sigmoid_f(float x) { return 1.0f / (1.0f + expf(-x)); }
__device__ __forceinline__ float relu_f(float x) { return fmaxf(x, 0.0f); }
__device__ __forceinline__ float gelu_tanh(float x) {
    float x3 = x * x * x;
    float t = tanhf(0.7978845608028654f * (x + 0.044715f * x3));
    return 0.5f * x * (1.0f + t);
}

// ---------------- kernel 0: zero accumulators (graph replays!) ---------------
__global__ void k_zero() {
    if (threadIdx.x < 8) g_acc[threadIdx.x] = 0.0f;
}

// ---------------- kernel 1: spectral weights + Gram sums ---------------------
// errA/errC via ||UU^T - I||_F^2 = ||U^T U||_F^2 - 2||U||_F^2 + n.
__global__ void __launch_bounds__(128) k_setup(
    const float* __restrict__ UA, const float* __restrict__ sigA, const float* __restrict__ VA,
    const float* __restrict__ UC, const float* __restrict__ sigC, const float* __restrict__ VC)
{
    __shared__ float sA[128], sC[64], rowUA[128], rowUC[64];
    __shared__ float colUA[128], colVA[128], colUC[128], colVC[64];
    __shared__ float red[4];
    int i = blockIdx.x, j = threadIdx.x;

    sA[j] = 0.1f + 0.8f * sigmoid_f(sigA[j]);
    rowUA[j] = UA[i * 128 + j];
    colUA[j] = UA[j * 128 + i];
    colVA[j] = VA[j * 128 + i];
    colUC[j] = UC[j * 128 + i];
    if (j < 64) {
        sC[j] = 0.9f + 0.1f * sigmoid_f(sigC[j]);
        rowUC[j] = UC[i * 128 + j];
        if (i < 64) colVC[j] = VC[j * 64 + i];
    }
    __syncthreads();

    // W_A row i
    float acc = 0.0f;
    #pragma unroll 8
    for (int k = 0; k < 128; k++) acc = fmaf(rowUA[k] * sA[k], VA[k * 128 + j], acc);
    g_WA[i * 128 + j] = acc;

    // W_C row i (cols < 64)
    if (j < 64) {
        float a = 0.0f;
        #pragma unroll 8
        for (int k = 0; k < 64; k++) a = fmaf(rowUC[k] * sC[k], VC[k * 64 + j], a);
        g_WC[i * 64 + j] = a;
    }

    // Gram entries (column-Gram; coalesced global reads)
    float gua = 0.0f, gva = 0.0f, guc = 0.0f;
    #pragma unroll 8
    for (int k = 0; k < 128; k++) {
        gua = fmaf(colUA[k], UA[k * 128 + j], gua);
        gva = fmaf(colVA[k], VA[k * 128 + j], gva);
        guc = fmaf(colUC[k], UC[k * 128 + j], guc);
    }
    float p6 = 0.0f, p7 = 0.0f;
    if (i < 64 && j < 64) {
        float g = 0.0f;
        #pragma unroll 8
        for (int k = 0; k < 64; k++) g = fmaf(colVC[k], VC[k * 64 + j], g);
        p6 = g * g;
        float v = VC[i * 64 + j];
        p7 = v * v;
    }
    float part[8];
    part[0] = gua * gua;
    part[1] = rowUA[j] * rowUA[j];
    part[2] = gva * gva;
    { float v = VA[i * 128 + j]; part[3] = v * v; }
    part[4] = guc * guc;
    { float v = UC[i * 128 + j]; part[5] = v * v; }
    part[6] = p6;
    part[7] = p7;

    for (int v = 0; v < 8; v++) {
        float x = part[v];
        #pragma unroll
        for (int o = 16; o; o >>= 1) x += __shfl_xor_sync(0xffffffffu, x, o);
        if ((j & 31) == 0) red[j >> 5] = x;
        __syncthreads();
        if (j == 0) atomicAdd(&g_acc[v], red[0] + red[1] + red[2] + red[3]);
        __syncthreads();
    }
}

// ---------------- kernel 2: W_E, W_B, bvec, SpectErr -------------------------
__global__ void __launch_bounds__(128) k_setup2(
    const float* __restrict__ x0c, const float* __restrict__ wE,
    const float* __restrict__ sE, const float* __restrict__ wB,
    float* __restrict__ out)
{
    __shared__ float xc[128];
    int j = threadIdx.x;
    xc[j] = x0c[j];
    __syncthreads();

    float b = 0.0f;
    #pragma unroll 8
    for (int k = 0; k < 128; k++) b = fmaf(xc[k], g_WA[k * 128 + j], b);
    g_bvec[j] = b;

    // W_E column j: softmax over the 32 rows, scaled elementwise
    float mx = -1e30f;
    for (int i = 0; i < 32; i++) mx = fmaxf(mx, wE[i * 128 + j]);
    float s = 0.0f;
    for (int i = 0; i < 32; i++) s += expf(wE[i * 128 + j] - mx);
    float inv = 1.0f / s;
    for (int i = 0; i < 32; i++) {
        float sm = expf(wE[i * 128 + j] - mx) * inv;
        float sc = 1.0f - 0.95f * sigmoid_f(sE[i * 128 + j]);
        g_WE[i * 128 + j] = sc * sm;
    }
    for (int idx = j; idx < NUc * NXc; idx += 128) g_WB[idx] = relu_f(wB[idx]);

    float errA = (g_acc[0] - 2.0f * g_acc[1] + 128.0f) * (1.0f / 16384.0f)
               + (g_acc[2] - 2.0f * g_acc[3] + 128.0f) * (1.0f / 16384.0f);
    float errC = (g_acc[4] - 2.0f * g_acc[5] + 128.0f) * (1.0f / 16384.0f)
               + (g_acc[6] - 2.0f * g_acc[7] + 64.0f) * (1.0f / 4096.0f);
    float sp = errA + errC;
    for (int idx = j; idx < NSTEPSc; idx += 128) out[OFF_SPECT + idx] = sp;
}

// ---------------- kernel 3: RNN warmup (one block per batch element) ---------
// 256 threads: tid=(j, h); thread holds half-columns of W_hh (64) and W_ih (32)
// in registers; h state broadcast from shared.
__global__ void __launch_bounds__(256) k_rnn(
    const float* __restrict__ Ym, const float* __restrict__ Wih,
    const float* __restrict__ Whh)
{
    __shared__ __align__(16) float h_sh[128];
    __shared__ __align__(16) float ym_sh[64];
    __shared__ float p_sh[128];
    int tid = threadIdx.x;
    int b = blockIdx.x;
    int j = tid & 127, hh = tid >> 7;

    float whh_r[64];
    #pragma unroll
    for (int kk = 0; kk < 64; kk++) whh_r[kk] = Whh[(hh * 64 + kk) * 128 + j];
    float wih_r[32];
    #pragma unroll
    for (int kk = 0; kk < 32; kk++) wih_r[kk] = Wih[(hh * 32 + kk) * 128 + j];

    if (tid < 128) h_sh[tid] = 0.0f;
    __syncthreads();

    for (int t = 0; t < TPc; t++) {
        if (tid < 64) ym_sh[tid] = Ym[((size_t)t * Bc + b) * 64 + tid];
        __syncthreads();
        float acc = 0.0f;
        const float4* y4 = ((const float4*)ym_sh) + hh * 8;
        #pragma unroll
        for (int kk = 0; kk < 8; kk++) {
            float4 yv = y4[kk];
            acc = fmaf(yv.x, wih_r[kk * 4 + 0], acc);
            acc = fmaf(yv.y, wih_r[kk * 4 + 1], acc);
            acc = fmaf(yv.z, wih_r[kk * 4 + 2], acc);
            acc = fmaf(yv.w, wih_r[kk * 4 + 3], acc);
        }
        const float4* h4 = ((const float4*)h_sh) + hh * 16;
        #pragma unroll
        for (int kk = 0; kk < 16; kk++) {
            float4 hv = h4[kk];
            acc = fmaf(hv.x, whh_r[kk * 4 + 0], acc);
            acc = fmaf(hv.y, whh_r[kk * 4 + 1], acc);
            acc = fmaf(hv.z, whh_r[kk * 4 + 2], acc);
            acc = fmaf(hv.w, whh_r[kk * 4 + 3], acc);
        }
        if (hh == 1) p_sh[j] = acc;
        __syncthreads();
        if (hh == 0) {
            float a = acc + p_sh[j];
            h_sh[j] = gelu_tanh(a);
        }
        __syncthreads();
    }
    if (tid < 128) g_x0[b * 128 + tid] = h_sh[tid];
}

// ---------------- kernel 4: precompute (bilinear u, Bu, Ed, slacks) ----------
// One block per step t; W_hf lives in registers (128 floats / thread as 32 float4),
// g = outer(m, dT) in shared, reused by all 256 threads per batch element.
__global__ void __launch_bounds__(256) k_pre(
    const float* __restrict__ M, const float* __restrict__ DTin,
    const float* __restrict__ Din, const float* __restrict__ UMIN,
    const float* __restrict__ UMAX, const float* __restrict__ Whf,
    const float* __restrict__ dxmn_g, const float* __restrict__ dxmx_g,
    float* __restrict__ out)
{
    __shared__ float wb_sh[NUc * NXc];   // 16 KB
    __shared__ float we_sh[NDc * NXc];   // 16 KB
    __shared__ float bvec_sh[NXc];
    __shared__ float dxmn_sh[NXc], dxmx_sh[NXc];
    __shared__ __align__(16) float g_sh[NMc * NDTc];  // 4 KB  outer(m, dT)
    __shared__ __align__(16) float m_sh[NMc];
    __shared__ __align__(16) float dt_sh[NDTc];
    __shared__ __align__(16) float d_sh[NDc];
    __shared__ float u_sh[NUc];

    int tid = threadIdx.x;
    int t = blockIdx.x;
    int o = tid >> 3, l = tid & 7;

    // W_hf -> registers: thread (o,l) holds W_hf[o][i][l*4 .. l*4+3] for all i
    float4 w[32];
    const float4* whf4 = (const float4*)Whf;
    #pragma unroll
    for (int i = 0; i < 32; i++) w[i] = whf4[(o * 32 + i) * 8 + l];

    for (int idx = tid; idx < NUc * NXc; idx += 256) wb_sh[idx] = g_WB[idx];
    for (int idx = tid; idx < NDc * NXc; idx += 256) we_sh[idx] = g_WE[idx];
    if (tid < 128) {
        bvec_sh[tid] = g_bvec[tid];
        dxmn_sh[tid] = dxmn_g[tid];
        dxmx_sh[tid] = dxmx_g[tid];
    }
    __syncthreads();

    for (int b = 0; b < Bc; b++) {
        size_t base32 = ((size_t)t * Bc + b) * 32;
        if (tid < 32)       m_sh[tid]       = M[base32 + tid];
        else if (tid < 64)  dt_sh[tid - 32] = DTin[base32 + tid - 32];
        else if (tid < 96)  d_sh[tid - 64]  = Din[base32 + tid - 64];
        __syncthreads();

        // g[i][j] = m[i] * dT[j]  (each thread writes one float4)
        {
            int idx = tid * 4;
            int gi = idx >> 5, gj4 = (idx & 31) >> 2;
            float4 dv = ((const float4*)dt_sh)[gj4];
            float mi = m_sh[gi];
            ((float4*)g_sh)[tid] = make_float4(mi * dv.x, mi * dv.y, mi * dv.z, mi * dv.w);
        }
        __syncthreads();

        // bilinear: u[o] = sum_{i,j} W_hf[o,i,j] * g[i,j]
        float acc = 0.0f;
        const float4* g4 = (const float4*)g_sh;
        #pragma unroll
        for (int i = 0; i < 32; i++) {
            float4 gv = g4[i * 8 + l];
            acc = fmaf(w[i].x, gv.x, acc);
            acc = fmaf(w[i].y, gv.y, acc);
            acc = fmaf(w[i].z, gv.z, acc);
            acc = fmaf(w[i].w, gv.w, acc);
        }
        acc += __shfl_xor_sync(0xffffffffu, acc, 1);
        acc += __shfl_xor_sync(0xffffffffu, acc, 2);
        acc += __shfl_xor_sync(0xffffffffu, acc, 4);
        if (l == 0) u_sh[o] = acc;
        __syncthreads();

        if (tid < 32) {
            size_t idx = base32 + tid;
            float uo = u_sh[tid];
            out[OFF_U + idx] = uo;
            out[OFF_SUMIN + idx] = relu_f(UMIN[idx] - uo);
            out[OFF_SUMAX + idx] = relu_f(uo - UMAX[idx]);
        }
        if (tid < 128) {
            int c = tid;
            float bu = 0.0f, ed = 0.0f;
            #pragma unroll 8
            for (int oo = 0; oo < 32; oo++) {
                bu = fmaf(u_sh[oo], wb_sh[oo * 128 + c], bu);
                ed = fmaf(d_sh[oo], we_sh[oo * 128 + c], ed);
            }
            size_t idx = ((size_t)t * Bc + b) * 128 + c;
            g_C[idx] = bu + ed + bvec_sh[c];
            float dn = dxmn_sh[c], dx = dxmx_sh[c];
            out[OFF_SDXU + idx] = relu_f(dn - bu) + relu_f(bu - dx);
            out[OFF_SDXD + idx] = relu_f(dn - ed) + relu_f(ed - dx);
        }
        __syncthreads();
    }
}

// ---------------- kernel 5: sequential rollout (one block per batch elem) ----
// 256 threads (j, h); W_A half-columns (64 regs) + W_C quarter-columns (32 regs)
// register-resident; x broadcast via shared (small -> shared BW not a bottleneck).
__global__ void __launch_bounds__(256) k_seq(
    const float* __restrict__ XMIN, const float* __restrict__ XMAX,
    float* __restrict__ out)
{
    __shared__ __align__(16) float x_sh[128];
    __shared__ float p_sh[128];
    __shared__ float yp_sh[256];
    int tid = threadIdx.x;
    int b = blockIdx.x;
    int j = tid & 127, hh = tid >> 7;
    int j2 = tid & 63, q = tid >> 6;

    float wa[64];
    #pragma unroll
    for (int kk = 0; kk < 64; kk++) wa[kk] = g_WA[(hh * 64 + kk) * 128 + j];
    float wc[32];
    #pragma unroll
    for (int kk = 0; kk < 32; kk++) wc[kk] = g_WC[(q * 32 + kk) * 64 + j2];

    if (tid < 128) x_sh[tid] = g_x0[b * 128 + tid];
    __syncthreads();

    for (int t = 0; t < NSTEPSc; t++) {
        size_t base = (size_t)t * Bc + b;
        size_t b128 = base * 128, b64 = base * 64;

        float cj = 0.0f, xmn = 0.0f, xmx = 0.0f, xold = 0.0f;
        if (hh == 0) {
            cj   = g_C[b128 + j];
            xmn  = XMIN[b128 + j];
            xmx  = XMAX[b128 + j];
            xold = x_sh[j];
        }

        float acc = 0.0f;
        const float4* x4 = ((const float4*)x_sh) + hh * 16;
        #pragma unroll
        for (int kk = 0; kk < 16; kk++) {
            float4 xv = x4[kk];
            acc = fmaf(xv.x, wa[kk * 4 + 0], acc);
            acc = fmaf(xv.y, wa[kk * 4 + 1], acc);
            acc = fmaf(xv.z, wa[kk * 4 + 2], acc);
            acc = fmaf(xv.w, wa[kk * 4 + 3], acc);
        }
        if (hh == 1) p_sh[j] = acc;
        __syncthreads();

        if (hh == 0) {
            float xn = acc + p_sh[j] + cj;
            out[OFF_X + b128 + j]     = xn;
            out[OFF_SXMIN + b128 + j] = relu_f(xmn - xn);
            out[OFF_SXMAX + b128 + j] = relu_f(xn - xmx);
            out[OFF_SDXX + b128 + j]  = xn - xold;
            x_sh[j] = xn;
        }
        __syncthreads();

        // Y = x_new @ W_C (k split 4 ways)
        float part = 0.0f;
        const float4* xc4 = ((const float4*)x_sh) + q * 8;
        #pragma unroll
        for (int kk = 0; kk < 8; kk++) {
            float4 xv = xc4[kk];
            part = fmaf(xv.x, wc[kk * 4 + 0], part);
            part = fmaf(xv.y, wc[kk * 4 + 1], part);
            part = fmaf(xv.z, wc[kk * 4 + 2], part);
            part = fmaf(xv.w, wc[kk * 4 + 3], part);
        }
        yp_sh[q * 64 + j2] = part;
        __syncthreads();
        if (tid < 64) {
            float y = yp_sh[tid] + yp_sh[64 + tid] + yp_sh[128 + tid] + yp_sh[192 + tid];
            out[OFF_Y + b64 + tid] = y;
        }
    }
}

// ---------------- launch ------------------------------------------------------
extern "C" void kernel_launch(void* const* d_in, const int* in_sizes, int n_in,
                              void* d_out, int out_size)
{
    const float* Ym   = (const float*)d_in[0];
    const float* M    = (const float*)d_in[1];
    const float* DTin = (const float*)d_in[2];
    const float* Din  = (const float*)d_in[3];
    const float* XMIN = (const float*)d_in[4];
    const float* XMAX = (const float*)d_in[5];
    const float* UMIN = (const float*)d_in[6];
    const float* UMAX = (const float*)d_in[7];
    const float* x0c  = (const float*)d_in[8];
    const float* UA   = (const float*)d_in[9];
    const float* sigA = (const float*)d_in[10];
    const float* VA   = (const float*)d_in[11];
    const float* UC   = (const float*)d_in[12];
    const float* sigC = (const float*)d_in[13];
    const float* VC   = (const float*)d_in[14];
    const float* wE   = (const float*)d_in[15];
    const float* sE   = (const float*)d_in[16];
    const float* wB   = (const float*)d_in[17];
    const float* Whf  = (const float*)d_in[18];
    const float* Wih  = (const float*)d_in[19];
    const float* Whh  = (const float*)d_in[20];
    const float* dxmn = (const float*)d_in[21];
    const float* dxmx = (const float*)d_in[22];
    float* out = (float*)d_out;

    k_zero<<<1, 32>>>();
    k_setup<<<128, 128>>>(UA, sigA, VA, UC, sigC, VC);
    k_setup2<<<1, 128>>>(x0c, wE, sE, wB, out);
    k_rnn<<<Bc, 256>>>(Ym, Wih, Whh);
    k_pre<<<NSTEPSc, 256>>>(M, DTin, Din, UMIN, UMAX, Whf, dxmn, dxmx, out);
    k_seq<<<Bc, 256>>>(XMIN, XMAX, out);
}

// round 3
// speedup vs baseline: 1.4703x; 1.4703x over previous
#include <cuda_runtime.h>
#include <math.h>

// Problem dims
#define NXc 128
#define NYc 64
#define NMc 32
#define NDTc 32
#define NUc 32
#define NDc 32
#define NSTEPSc 1024
#define Bc 128
#define TPc 64

// Output offsets (floats) for the flattened 11-tuple
#define OFF_X      ((size_t)0)
#define OFF_Y      ((size_t)16777216)
#define OFF_U      ((size_t)25165824)
#define OFF_SXMIN  ((size_t)29360128)
#define OFF_SXMAX  ((size_t)46137344)
#define OFF_SUMIN  ((size_t)62914560)
#define OFF_SUMAX  ((size_t)67108864)
#define OFF_SDXX   ((size_t)71303168)
#define OFF_SDXU   ((size_t)88080384)
#define OFF_SDXD   ((size_t)104857600)
#define OFF_SPECT  ((size_t)121634816)

// ---------------- module-scope scratch ----------------
__device__ float g_WA[NXc * NXc];
__device__ float g_WC[NXc * NYc];
__device__ float g_WE[NDc * NXc];
__device__ float g_WB[NUc * NXc];
__device__ float g_bvec[NXc];
__device__ float g_x0[Bc * NXc];
__device__ float g_C[(size_t)NSTEPSc * Bc * NXc];
__device__ float g_acc[8];

__device__ __forceinline__ float sigmoid_f(float x) { return 1.0f / (1.0f + expf(-x)); }
__device__ __forceinline__ float relu_f(float x) { return fmaxf(x, 0.0f); }
__device__ __forceinline__ float gelu_tanh(float x) {
    float x3 = x * x * x;
    float t = tanhf(0.7978845608028654f * (x + 0.044715f * x3));
    return 0.5f * x * (1.0f + t);
}

// ---------------- kernel 0: zero accumulators --------------------------------
__global__ void k_zero() {
    if (threadIdx.x < 8) g_acc[threadIdx.x] = 0.0f;
}

// ---------------- kernel 1: spectral weights + Gram sums ---------------------
__global__ void __launch_bounds__(128) k_setup(
    const float* __restrict__ UA, const float* __restrict__ sigA, const float* __restrict__ VA,
    const float* __restrict__ UC, const float* __restrict__ sigC, const float* __restrict__ VC)
{
    __shared__ float sA[128], sC[64], rowUA[128], rowUC[64];
    __shared__ float colUA[128], colVA[128], colUC[128], colVC[64];
    __shared__ float red[4];
    int i = blockIdx.x, j = threadIdx.x;

    sA[j] = 0.1f + 0.8f * sigmoid_f(sigA[j]);
    rowUA[j] = UA[i * 128 + j];
    colUA[j] = UA[j * 128 + i];
    colVA[j] = VA[j * 128 + i];
    colUC[j] = UC[j * 128 + i];
    if (j < 64) {
        sC[j] = 0.9f + 0.1f * sigmoid_f(sigC[j]);
        rowUC[j] = UC[i * 128 + j];
        if (i < 64) colVC[j] = VC[j * 64 + i];
    }
    __syncthreads();

    float acc = 0.0f;
    #pragma unroll 8
    for (int k = 0; k < 128; k++) acc = fmaf(rowUA[k] * sA[k], VA[k * 128 + j], acc);
    g_WA[i * 128 + j] = acc;

    if (j < 64) {
        float a = 0.0f;
        #pragma unroll 8
        for (int k = 0; k < 64; k++) a = fmaf(rowUC[k] * sC[k], VC[k * 64 + j], a);
        g_WC[i * 64 + j] = a;
    }

    float gua = 0.0f, gva = 0.0f, guc = 0.0f;
    #pragma unroll 8
    for (int k = 0; k < 128; k++) {
        gua = fmaf(colUA[k], UA[k * 128 + j], gua);
        gva = fmaf(colVA[k], VA[k * 128 + j], gva);
        guc = fmaf(colUC[k], UC[k * 128 + j], guc);
    }
    float p6 = 0.0f, p7 = 0.0f;
    if (i < 64 && j < 64) {
        float g = 0.0f;
        #pragma unroll 8
        for (int k = 0; k < 64; k++) g = fmaf(colVC[k], VC[k * 64 + j], g);
        p6 = g * g;
        float v = VC[i * 64 + j];
        p7 = v * v;
    }
    float part[8];
    part[0] = gua * gua;
    part[1] = rowUA[j] * rowUA[j];
    part[2] = gva * gva;
    { float v = VA[i * 128 + j]; part[3] = v * v; }
    part[4] = guc * guc;
    { float v = UC[i * 128 + j]; part[5] = v * v; }
    part[6] = p6;
    part[7] = p7;

    for (int v = 0; v < 8; v++) {
        float x = part[v];
        #pragma unroll
        for (int o = 16; o; o >>= 1) x += __shfl_xor_sync(0xffffffffu, x, o);
        if ((j & 31) == 0) red[j >> 5] = x;
        __syncthreads();
        if (j == 0) atomicAdd(&g_acc[v], red[0] + red[1] + red[2] + red[3]);
        __syncthreads();
    }
}

// ---------------- kernel 2: W_E, W_B, bvec, SpectErr -------------------------
__global__ void __launch_bounds__(128) k_setup2(
    const float* __restrict__ x0c, const float* __restrict__ wE,
    const float* __restrict__ sE, const float* __restrict__ wB,
    float* __restrict__ out)
{
    __shared__ float xc[128];
    int j = threadIdx.x;
    xc[j] = x0c[j];
    __syncthreads();

    float b = 0.0f;
    #pragma unroll 8
    for (int k = 0; k < 128; k++) b = fmaf(xc[k], g_WA[k * 128 + j], b);
    g_bvec[j] = b;

    float mx = -1e30f;
    for (int i = 0; i < 32; i++) mx = fmaxf(mx, wE[i * 128 + j]);
    float s = 0.0f;
    for (int i = 0; i < 32; i++) s += expf(wE[i * 128 + j] - mx);
    float inv = 1.0f / s;
    for (int i = 0; i < 32; i++) {
        float sm = expf(wE[i * 128 + j] - mx) * inv;
        float sc = 1.0f - 0.95f * sigmoid_f(sE[i * 128 + j]);
        g_WE[i * 128 + j] = sc * sm;
    }
    for (int idx = j; idx < NUc * NXc; idx += 128) g_WB[idx] = relu_f(wB[idx]);

    float errA = (g_acc[0] - 2.0f * g_acc[1] + 128.0f) * (1.0f / 16384.0f)
               + (g_acc[2] - 2.0f * g_acc[3] + 128.0f) * (1.0f / 16384.0f);
    float errC = (g_acc[4] - 2.0f * g_acc[5] + 128.0f) * (1.0f / 16384.0f)
               + (g_acc[6] - 2.0f * g_acc[7] + 64.0f) * (1.0f / 4096.0f);
    float sp = errA + errC;
    for (int idx = j; idx < NSTEPSc; idx += 128) out[OFF_SPECT + idx] = sp;
}

// ---------------- kernel 3: RNN warmup (512 thr, 4-way K split) --------------
__global__ void __launch_bounds__(512) k_rnn(
    const float* __restrict__ Ym, const float* __restrict__ Wih,
    const float* __restrict__ Whh)
{
    __shared__ float h_sh[128];
    __shared__ float ym_sh[2][64];
    __shared__ float p_sh[3 * 128];
    int tid = threadIdx.x;
    int b = blockIdx.x;
    int j = tid & 127, h = tid >> 7;

    float whh_r[32];
    #pragma unroll
    for (int kk = 0; kk < 32; kk++) whh_r[kk] = Whh[(h * 32 + kk) * 128 + j];
    float wih_r[16];
    #pragma unroll
    for (int kk = 0; kk < 16; kk++) wih_r[kk] = Wih[(h * 16 + kk) * 128 + j];

    if (tid < 128) h_sh[tid] = 0.0f;
    if (tid >= 448) ym_sh[0][tid - 448] = Ym[(size_t)b * 64 + (tid - 448)];
    __syncthreads();

    for (int t = 0; t < TPc; t++) {
        const float* yc = ym_sh[t & 1];
        float acc = 0.0f;
        #pragma unroll
        for (int kk = 0; kk < 16; kk++)
            acc = fmaf(yc[h * 16 + kk], wih_r[kk], acc);
        #pragma unroll
        for (int kk = 0; kk < 32; kk++)
            acc = fmaf(h_sh[h * 32 + kk], whh_r[kk], acc);

        // prefetch next Ym row into the other buffer
        if (tid >= 448 && t + 1 < TPc)
            ym_sh[(t + 1) & 1][tid - 448] = Ym[((size_t)(t + 1) * Bc + b) * 64 + (tid - 448)];

        if (h) p_sh[(h - 1) * 128 + j] = acc;
        __syncthreads();
        if (h == 0)
            h_sh[j] = gelu_tanh(acc + p_sh[j] + p_sh[128 + j] + p_sh[256 + j]);
        __syncthreads();
    }
    if (tid < 128) g_x0[b * 128 + tid] = h_sh[tid];
}

// ---------------- kernel 4: precompute (u, Bu, Ed, slacks) -------------------
// One block per t. All inputs for the block loaded upfront into dynamic smem.
// Thread (o=tid>>3, l=tid&7) holds W_hf[o][*][l*4..l*4+3] in registers.
// tid<128 additionally holds W_B/W_E column tid in registers.
#define SM_PRE_FLOATS (4096*3 + 1024 + 128*3 + 32)
__global__ void __launch_bounds__(256) k_pre(
    const float* __restrict__ M, const float* __restrict__ DTin,
    const float* __restrict__ Din, const float* __restrict__ UMIN,
    const float* __restrict__ UMAX, const float* __restrict__ Whf,
    const float* __restrict__ dxmn_g, const float* __restrict__ dxmx_g,
    float* __restrict__ out)
{
    extern __shared__ float sm[];
    float* m_all  = sm;                 // 4096
    float* dt_all = sm + 4096;          // 4096
    float* d_all  = sm + 8192;          // 4096
    float* g_sh   = sm + 12288;         // 1024
    float* bvec_sh = sm + 13312;        // 128
    float* dxmn_sh = sm + 13440;        // 128
    float* dxmx_sh = sm + 13568;        // 128
    float* u_sh    = sm + 13696;        // 32

    int tid = threadIdx.x;
    int t = blockIdx.x;
    int o = tid >> 3, l = tid & 7;

    // W_hf -> registers
    float4 w[32];
    const float4* whf4 = (const float4*)Whf;
    #pragma unroll
    for (int i = 0; i < 32; i++) w[i] = whf4[(o * 32 + i) * 8 + l];

    // W_B / W_E columns -> registers (threads 0..127)
    float wb_r[32], we_r[32];
    if (tid < 128) {
        #pragma unroll
        for (int oo = 0; oo < 32; oo++) {
            wb_r[oo] = g_WB[oo * 128 + tid];
            we_r[oo] = g_WE[oo * 128 + tid];
        }
    }

    // bulk-load this t's inputs
    size_t tb = (size_t)t * 4096;
    for (int idx = tid; idx < 4096; idx += 256) {
        m_all[idx]  = M[tb + idx];
        dt_all[idx] = DTin[tb + idx];
        d_all[idx]  = Din[tb + idx];
    }
    if (tid < 128) {
        bvec_sh[tid] = g_bvec[tid];
        dxmn_sh[tid] = dxmn_g[tid];
        dxmx_sh[tid] = dxmx_g[tid];
    }
    // UMIN/UMAX prefetch (threads 128..159 own output o' = tid-128)
    int uo_id = tid - 128;
    float umn_pf = 0.0f, umx_pf = 0.0f;
    if (uo_id >= 0 && uo_id < 32) {
        umn_pf = UMIN[tb + uo_id];
        umx_pf = UMAX[tb + uo_id];
    }
    __syncthreads();

    for (int b = 0; b < Bc; b++) {
        // S0: g[i][j] = m[i]*dT[j] (one float4 per thread)
        {
            int idx = tid * 4;
            int gi = idx >> 5, gj4 = (idx & 31) >> 2;
            float4 dv = ((const float4*)(dt_all + b * 32))[gj4];
            float mi = m_all[b * 32 + gi];
            ((float4*)g_sh)[tid] = make_float4(mi * dv.x, mi * dv.y, mi * dv.z, mi * dv.w);
        }
        __syncthreads();

        // S1: bilinear reduction
        float acc = 0.0f;
        const float4* g4 = (const float4*)g_sh;
        #pragma unroll
        for (int i = 0; i < 32; i++) {
            float4 gv = g4[i * 8 + l];
            acc = fmaf(w[i].x, gv.x, acc);
            acc = fmaf(w[i].y, gv.y, acc);
            acc = fmaf(w[i].z, gv.z, acc);
            acc = fmaf(w[i].w, gv.w, acc);
        }
        // prefetch UMIN/UMAX for b+1
        float umn_nx = 0.0f, umx_nx = 0.0f;
        if (uo_id >= 0 && uo_id < 32 && b + 1 < Bc) {
            umn_nx = UMIN[tb + (size_t)(b + 1) * 32 + uo_id];
            umx_nx = UMAX[tb + (size_t)(b + 1) * 32 + uo_id];
        }
        acc += __shfl_xor_sync(0xffffffffu, acc, 1);
        acc += __shfl_xor_sync(0xffffffffu, acc, 2);
        acc += __shfl_xor_sync(0xffffffffu, acc, 4);
        if (l == 0) u_sh[o] = acc;
        __syncthreads();

        // S2: outputs
        size_t base32  = tb + (size_t)b * 32;
        size_t base128 = ((size_t)t * Bc + b) * 128;
        if (tid < 128) {
            float bu = 0.0f, ed = 0.0f;
            #pragma unroll
            for (int oo = 0; oo < 32; oo++) {
                bu = fmaf(u_sh[oo], wb_r[oo], bu);
                ed = fmaf(d_all[b * 32 + oo], we_r[oo], ed);
            }
            float dn = dxmn_sh[tid], dx = dxmx_sh[tid];
            out[OFF_SDXU + base128 + tid] = relu_f(dn - bu) + relu_f(bu - dx);
            out[OFF_SDXD + base128 + tid] = relu_f(dn - ed) + relu_f(ed - dx);
            g_C[base128 + tid] = bu + ed + bvec_sh[tid];
        } else if (uo_id < 32) {
            float uo = u_sh[uo_id];
            out[OFF_U + base32 + uo_id]     = uo;
            out[OFF_SUMIN + base32 + uo_id] = relu_f(umn_pf - uo);
            out[OFF_SUMAX + base32 + uo_id] = relu_f(uo - umx_pf);
            umn_pf = umn_nx;
            umx_pf = umx_nx;
        }
        __syncthreads();
    }
}

// ---------------- kernel 5: sequential rollout (512 thr, prefetch depth 2) ---
__global__ void __launch_bounds__(512) k_seq(
    const float* __restrict__ XMIN, const float* __restrict__ XMAX,
    const float* __restrict__ Cg, float* __restrict__ out)
{
    __shared__ float x_sh[128];
    __shared__ float p_sh[3 * 128];
    int tid = threadIdx.x;
    int b = blockIdx.x;
    int j = tid & 127, h = tid >> 7;

    float wa[32];
    #pragma unroll
    for (int kk = 0; kk < 32; kk++) wa[kk] = g_WA[(h * 32 + kk) * 128 + j];

    if (tid < 128) x_sh[tid] = g_x0[b * 128 + tid];

    float c0 = 0, c1 = 0, mn0 = 0, mn1 = 0, mx0 = 0, mx1 = 0;
    if (h == 0) {
        size_t i0 = ((size_t)0 * Bc + b) * 128 + j;
        size_t i1 = ((size_t)1 * Bc + b) * 128 + j;
        c0 = Cg[i0]; mn0 = XMIN[i0]; mx0 = XMAX[i0];
        c1 = Cg[i1]; mn1 = XMIN[i1]; mx1 = XMAX[i1];
    }
    __syncthreads();

    for (int t = 0; t < NSTEPSc; t++) {
        float acc = 0.0f;
        const float4* x4 = ((const float4*)x_sh) + h * 8;
        #pragma unroll
        for (int kk = 0; kk < 8; kk++) {
            float4 xv = x4[kk];
            acc = fmaf(xv.x, wa[kk * 4 + 0], acc);
            acc = fmaf(xv.y, wa[kk * 4 + 1], acc);
            acc = fmaf(xv.z, wa[kk * 4 + 2], acc);
            acc = fmaf(xv.w, wa[kk * 4 + 3], acc);
        }
        // prefetch t+2
        float cn = 0, mnn = 0, mxn = 0;
        if (h == 0 && t + 2 < NSTEPSc) {
            size_t i2 = ((size_t)(t + 2) * Bc + b) * 128 + j;
            cn = Cg[i2]; mnn = XMIN[i2]; mxn = XMAX[i2];
        }
        if (h) p_sh[(h - 1) * 128 + j] = acc;
        __syncthreads();

        if (h == 0) {
            float xold = x_sh[j];
            float xn = acc + p_sh[j] + p_sh[128 + j] + p_sh[256 + j] + c0;
            size_t bi = ((size_t)t * Bc + b) * 128 + j;
            out[OFF_X + bi]     = xn;
            out[OFF_SXMIN + bi] = relu_f(mn0 - xn);
            out[OFF_SXMAX + bi] = relu_f(xn - mx0);
            out[OFF_SDXX + bi]  = xn - xold;
            x_sh[j] = xn;
            c0 = c1; mn0 = mn1; mx0 = mx1;
            c1 = cn; mn1 = mnn; mx1 = mxn;
        }
        __syncthreads();
    }
}

// ---------------- kernel 6: Y = X @ W_C (fully parallel) ---------------------
// 256 threads / block, 2 rows (t,b pairs) per block, k split 2 ways.
__global__ void __launch_bounds__(256) k_post(float* __restrict__ out)
{
    __shared__ float x2[256];
    __shared__ float p2[128];
    int tid = threadIdx.x;
    size_t row0 = (size_t)blockIdx.x * 2;
    int r = tid >> 7;
    int q = (tid >> 6) & 1, j2 = tid & 63;

    float wc[64];
    #pragma unroll
    for (int kk = 0; kk < 64; kk++) wc[kk] = g_WC[(q * 64 + kk) * 64 + j2];

    x2[tid] = out[OFF_X + row0 * 128 + tid];
    __syncthreads();

    float part = 0.0f;
    const float* xr = x2 + r * 128 + q * 64;
    #pragma unroll
    for (int kk = 0; kk < 64; kk++) part = fmaf(xr[kk], wc[kk], part);

    if (q == 1) p2[r * 64 + j2] = part;
    __syncthreads();
    if (q == 0)
        out[OFF_Y + row0 * 64 + (size_t)r * 64 + j2] = part + p2[r * 64 + j2];
}

// ---------------- launch ------------------------------------------------------
extern "C" void kernel_launch(void* const* d_in, const int* in_sizes, int n_in,
                              void* d_out, int out_size)
{
    const float* Ym   = (const float*)d_in[0];
    const float* M    = (const float*)d_in[1];
    const float* DTin = (const float*)d_in[2];
    const float* Din  = (const float*)d_in[3];
    const float* XMIN = (const float*)d_in[4];
    const float* XMAX = (const float*)d_in[5];
    const float* UMIN = (const float*)d_in[6];
    const float* UMAX = (const float*)d_in[7];
    const float* x0c  = (const float*)d_in[8];
    const float* UA   = (const float*)d_in[9];
    const float* sigA = (const float*)d_in[10];
    const float* VA   = (const float*)d_in[11];
    const float* UC   = (const float*)d_in[12];
    const float* sigC = (const float*)d_in[13];
    const float* VC   = (const float*)d_in[14];
    const float* wE   = (const float*)d_in[15];
    const float* sE   = (const float*)d_in[16];
    const float* wB   = (const float*)d_in[17];
    const float* Whf  = (const float*)d_in[18];
    const float* Wih  = (const float*)d_in[19];
    const float* Whh  = (const float*)d_in[20];
    const float* dxmn = (const float*)d_in[21];
    const float* dxmx = (const float*)d_in[22];
    float* out = (float*)d_out;

    static const size_t smem_pre = SM_PRE_FLOATS * sizeof(float);
    cudaFuncSetAttribute(k_pre, cudaFuncAttributeMaxDynamicSharedMemorySize,
                         (int)smem_pre);

    float* Cg = nullptr;
    cudaGetSymbolAddress((void**)&Cg, g_C);

    k_zero<<<1, 32>>>();
    k_setup<<<128, 128>>>(UA, sigA, VA, UC, sigC, VC);
    k_setup2<<<1, 128>>>(x0c, wE, sE, wB, out);
    k_rnn<<<Bc, 512>>>(Ym, Wih, Whh);
    k_pre<<<NSTEPSc, 256, smem_pre>>>(M, DTin, Din, UMIN, UMAX, Whf, dxmn, dxmx, out);
    k_seq<<<Bc, 512>>>(XMIN, XMAX, Cg, out);
    k_post<<<(NSTEPSc * Bc) / 2, 256>>>(out);
}